// round 1
// baseline (speedup 1.0000x reference)
#include <cuda_runtime.h>
#include <math.h>

#define Bc 32
#define Nn 784
#define DIMc 512
#define Hh 8
#define KDc 32
#define VDc 128
#define QKV_OUTc 1536
#define VAL_ATTNc 1024
#define SCALE 0.17677669529663687f

// ---------------- scratch (static device globals; allowed workaround) ----------------
__device__ float g_q[Bc * Hh * Nn * KDc];          // [b][h][n][32]
__device__ float g_k[Bc * Hh * Nn * KDc];          // [b][h][n][32]
__device__ float g_v[Bc * Hh * Nn * VDc];          // [b][h][n][128]
__device__ float g_o[Bc * Nn * VAL_ATTNc];         // [b][n][h*128+d]
__device__ float g_bias[Hh * Nn * Nn];             // [h][n][m]
__device__ float g_qs[QKV_OUTc], g_qbb[QKV_OUTc];
__device__ float g_ps[DIMc], g_pbb[DIMc];

// ---------------- f32x2 helpers (FFMA2: 2x fp32 FMA rate on sm_103a) ----------------
static __device__ __forceinline__ unsigned long long pack2(float lo, float hi) {
    unsigned long long r;
    asm("mov.b64 %0, {%1, %2};" : "=l"(r) : "r"(__float_as_uint(lo)), "r"(__float_as_uint(hi)));
    return r;
}
static __device__ __forceinline__ float2 unpack2(unsigned long long v) {
    unsigned int lo, hi;
    asm("mov.b64 {%0, %1}, %2;" : "=r"(lo), "=r"(hi) : "l"(v));
    return make_float2(__uint_as_float(lo), __uint_as_float(hi));
}
static __device__ __forceinline__ void fma2(unsigned long long& d, unsigned long long a, unsigned long long b) {
    asm("fma.rn.f32x2 %0, %1, %2, %0;" : "+l"(d) : "l"(a), "l"(b));
}

// ---------------- BN coefficient folding ----------------
__global__ void bn_coef_kernel(const float* __restrict__ qg, const float* __restrict__ qb,
                               const float* __restrict__ qm, const float* __restrict__ qv,
                               const float* __restrict__ pg, const float* __restrict__ pb,
                               const float* __restrict__ pm, const float* __restrict__ pv) {
    int i = blockIdx.x * 256 + threadIdx.x;
    if (i < QKV_OUTc) {
        float s = qg[i] * rsqrtf(qv[i] + 1e-5f);
        g_qs[i] = s;
        g_qbb[i] = qb[i] - qm[i] * s;
    }
    if (i < DIMc) {
        float s = pg[i] * rsqrtf(pv[i] + 1e-5f);
        g_ps[i] = s;
        g_pbb[i] = pb[i] - pm[i] * s;
    }
}

// ---------------- bias gather: g_bias[h][n][m] = ab[h, idxs[n,m]] ----------------
__global__ void bias_kernel(const float* __restrict__ ab, const int* __restrict__ idxs) {
    int nm = blockIdx.x * 256 + threadIdx.x;
    if (nm < Nn * Nn) {
        int idx = idxs[nm];
#pragma unroll
        for (int h = 0; h < Hh; h++)
            g_bias[h * Nn * Nn + nm] = ab[h * Nn + idx];
    }
}

// ---------------- QKV GEMM: C[m,o] = sum_k x[m,k]*w[o,k], + BN, scatter ----------------
static __device__ __forceinline__ void qkv_scatter(int b, int n, int o, float y) {
    int h = o / 192, r = o - h * 192;
    if (r < KDc)            g_q[((b * Hh + h) * Nn + n) * KDc + r] = y;
    else if (r < 2 * KDc)   g_k[((b * Hh + h) * Nn + n) * KDc + (r - KDc)] = y;
    else                    g_v[((b * Hh + h) * Nn + n) * VDc + (r - 2 * KDc)] = y;
}

__global__ __launch_bounds__(256, 2) void qkv_gemm_kernel(const float* __restrict__ x,
                                                          const float* __restrict__ w) {
    __shared__ float As[16][136];   // [k][row], padded
    __shared__ float Bs[16][136];
    int m0 = blockIdx.x * 128, o0 = blockIdx.y * 128;
    int t = threadIdx.x, tx = t & 15, ty = t >> 4;

    unsigned long long acc[8][4];
#pragma unroll
    for (int i = 0; i < 8; i++)
#pragma unroll
        for (int j = 0; j < 4; j++) acc[i][j] = 0ull;

    for (int k0 = 0; k0 < DIMc; k0 += 16) {
#pragma unroll
        for (int ii = 0; ii < 2; ii++) {
            int e = t + 256 * ii;
            int row = e >> 2, c4 = e & 3;
            float4 a = *(const float4*)(x + (m0 + row) * DIMc + k0 + 4 * c4);
            As[4 * c4 + 0][row] = a.x; As[4 * c4 + 1][row] = a.y;
            As[4 * c4 + 2][row] = a.z; As[4 * c4 + 3][row] = a.w;
            float4 bvec = *(const float4*)(w + (o0 + row) * DIMc + k0 + 4 * c4);
            Bs[4 * c4 + 0][row] = bvec.x; Bs[4 * c4 + 1][row] = bvec.y;
            Bs[4 * c4 + 2][row] = bvec.z; Bs[4 * c4 + 3][row] = bvec.w;
        }
        __syncthreads();
#pragma unroll
        for (int kk = 0; kk < 16; kk++) {
            unsigned long long a2[8], b2[4];
#pragma unroll
            for (int i = 0; i < 8; i++) { float av = As[kk][8 * ty + i]; a2[i] = pack2(av, av); }
#pragma unroll
            for (int j = 0; j < 4; j++) {
                float2 bv = *(const float2*)&Bs[kk][2 * tx + 32 * j];
                b2[j] = pack2(bv.x, bv.y);
            }
#pragma unroll
            for (int i = 0; i < 8; i++)
#pragma unroll
                for (int j = 0; j < 4; j++) fma2(acc[i][j], a2[i], b2[j]);
        }
        __syncthreads();
    }
#pragma unroll
    for (int i = 0; i < 8; i++) {
        int m = m0 + 8 * ty + i;
        int b = m / Nn, n = m - b * Nn;
#pragma unroll
        for (int j = 0; j < 4; j++) {
            int o = o0 + 2 * tx + 32 * j;
            float2 v2 = unpack2(acc[i][j]);
            qkv_scatter(b, n, o,     v2.x * g_qs[o]     + g_qbb[o]);
            qkv_scatter(b, n, o + 1, v2.y * g_qs[o + 1] + g_qbb[o + 1]);
        }
    }
}

// ---------------- attention: per (b,h,64-row q tile); no-max online softmax ----------------
__global__ __launch_bounds__(256) void attn_kernel() {
    extern __shared__ float sm[];
    float* q_s = sm;              // [32][68]  (k-major, padded)
    float* k_s = q_s + 32 * 68;   // [32][68]
    float* v_s = k_s + 32 * 68;   // [64][128]
    float* p_s = v_s + 64 * 128;  // [64 col][69 row]

    int n0 = blockIdx.x * 64;
    int h = blockIdx.y, b = blockIdx.z;
    int t = threadIdx.x, tx = t & 15, ty = t >> 4;

    const float* qb = g_q + ((b * Hh + h) * Nn) * KDc;
    const float* kb = g_k + ((b * Hh + h) * Nn) * KDc;
    const float* vb = g_v + ((b * Hh + h) * Nn) * VDc;
    const float* biasb = g_bias + h * Nn * Nn;

    for (int e = t; e < 2048; e += 256) {
        int r = e >> 5, kk = e & 31;
        int n = n0 + r;
        q_s[kk * 68 + r] = (n < Nn) ? qb[n * KDc + kk] : 0.f;
    }

    unsigned long long o_acc[4][4];
#pragma unroll
    for (int i = 0; i < 4; i++)
#pragma unroll
        for (int c = 0; c < 4; c++) o_acc[i][c] = 0ull;
    float rsum[4] = {0.f, 0.f, 0.f, 0.f};

    for (int m0 = 0; m0 < Nn; m0 += 64) {
        __syncthreads();   // previous-iteration readers done before overwrite
        for (int e = t; e < 2048; e += 256) {
            int r = e >> 5, kk = e & 31;
            int m = m0 + r;
            k_s[kk * 68 + r] = (m < Nn) ? kb[m * KDc + kk] : 0.f;
        }
        for (int e = t; e < 8192; e += 256) {
            int r = e >> 7, c = e & 127;
            int m = m0 + r;
            v_s[r * 128 + c] = (m < Nn) ? vb[m * VDc + c] : 0.f;
        }
        __syncthreads();

        // ---- S = Q K^T (64x64, K=32), f32x2 packed over col pairs ----
        unsigned long long sa[4][2];
#pragma unroll
        for (int i = 0; i < 4; i++) { sa[i][0] = 0ull; sa[i][1] = 0ull; }
#pragma unroll 8
        for (int kk = 0; kk < 32; kk++) {
            unsigned long long a2[4], b2[2];
#pragma unroll
            for (int i = 0; i < 4; i++) { float av = q_s[kk * 68 + 4 * ty + i]; a2[i] = pack2(av, av); }
#pragma unroll
            for (int j2 = 0; j2 < 2; j2++) {
                float2 kv = *(const float2*)&k_s[kk * 68 + 4 * tx + 2 * j2];
                b2[j2] = pack2(kv.x, kv.y);
            }
#pragma unroll
            for (int i = 0; i < 4; i++)
#pragma unroll
                for (int j2 = 0; j2 < 2; j2++) fma2(sa[i][j2], a2[i], b2[j2]);
        }

        // ---- bias + exp -> p_s (transposed [col][row]), accumulate row sums ----
#pragma unroll
        for (int i = 0; i < 4; i++) {
            int n = n0 + 4 * ty + i;
            int nc = (n < Nn) ? n : 0;
            const float* brow = biasb + nc * Nn + m0 + 4 * tx;
            float bias4[4];
            if (m0 + 4 * tx + 3 < Nn) {
                float4 bv = *(const float4*)brow;
                bias4[0] = bv.x; bias4[1] = bv.y; bias4[2] = bv.z; bias4[3] = bv.w;
            } else {
#pragma unroll
                for (int jj = 0; jj < 4; jj++) {
                    int m = m0 + 4 * tx + jj;
                    bias4[jj] = (m < Nn) ? brow[jj] : 0.f;
                }
            }
#pragma unroll
            for (int j2 = 0; j2 < 2; j2++) {
                float2 sv = unpack2(sa[i][j2]);
                int mA = m0 + 4 * tx + 2 * j2;
                float p0 = (mA     < Nn) ? __expf(sv.x * SCALE + bias4[2 * j2 + 0]) : 0.f;
                float p1 = (mA + 1 < Nn) ? __expf(sv.y * SCALE + bias4[2 * j2 + 1]) : 0.f;
                p_s[(4 * tx + 2 * j2 + 0) * 69 + 4 * ty + i] = p0;
                p_s[(4 * tx + 2 * j2 + 1) * 69 + 4 * ty + i] = p1;
                rsum[i] += p0 + p1;
            }
        }
        __syncthreads();

        // ---- O += P V (64x128, K=64), f32x2 packed over col pairs ----
#pragma unroll 8
        for (int j = 0; j < 64; j++) {
            unsigned long long pf[4], vf[4];
#pragma unroll
            for (int ii = 0; ii < 4; ii++) { float pv = p_s[j * 69 + 4 * ty + ii]; pf[ii] = pack2(pv, pv); }
#pragma unroll
            for (int c2 = 0; c2 < 4; c2++) {
                float2 vv = *(const float2*)&v_s[j * 128 + 2 * tx + 32 * c2];
                vf[c2] = pack2(vv.x, vv.y);
            }
#pragma unroll
            for (int ii = 0; ii < 4; ii++)
#pragma unroll
                for (int c2 = 0; c2 < 4; c2++) fma2(o_acc[ii][c2], pf[ii], vf[c2]);
        }
    }

    // row-sum reduce across the 16 tx lanes of each row group
#pragma unroll
    for (int i = 0; i < 4; i++)
#pragma unroll
        for (int off = 8; off > 0; off >>= 1)
            rsum[i] += __shfl_xor_sync(0xffffffffu, rsum[i], off, 16);

    // normalize + hardswish + store
#pragma unroll
    for (int ii = 0; ii < 4; ii++) {
        int n = n0 + 4 * ty + ii;
        if (n >= Nn) continue;
        float inv = 1.f / rsum[ii];
#pragma unroll
        for (int c2 = 0; c2 < 4; c2++) {
            float2 ov = unpack2(o_acc[ii][c2]);
            float o0v = ov.x * inv, o1v = ov.y * inv;
            o0v = o0v * fminf(fmaxf(o0v + 3.f, 0.f), 6.f) * (1.f / 6.f);
            o1v = o1v * fminf(fmaxf(o1v + 3.f, 0.f), 6.f) * (1.f / 6.f);
            *(float2*)&g_o[(b * Nn + n) * VAL_ATTNc + h * VDc + 2 * tx + 32 * c2] =
                make_float2(o0v, o1v);
        }
    }
}

// ---------------- proj GEMM: out[m,o] = BN(sum_k g_o[m,k]*w[o,k]) ----------------
__global__ __launch_bounds__(256, 2) void proj_gemm_kernel(const float* __restrict__ w,
                                                           float* __restrict__ out) {
    __shared__ float As[16][136];
    __shared__ float Bs[16][136];
    int m0 = blockIdx.x * 128, o0 = blockIdx.y * 128;
    int t = threadIdx.x, tx = t & 15, ty = t >> 4;

    unsigned long long acc[8][4];
#pragma unroll
    for (int i = 0; i < 8; i++)
#pragma unroll
        for (int j = 0; j < 4; j++) acc[i][j] = 0ull;

    for (int k0 = 0; k0 < VAL_ATTNc; k0 += 16) {
#pragma unroll
        for (int ii = 0; ii < 2; ii++) {
            int e = t + 256 * ii;
            int row = e >> 2, c4 = e & 3;
            float4 a = *(const float4*)(g_o + (m0 + row) * VAL_ATTNc + k0 + 4 * c4);
            As[4 * c4 + 0][row] = a.x; As[4 * c4 + 1][row] = a.y;
            As[4 * c4 + 2][row] = a.z; As[4 * c4 + 3][row] = a.w;
            float4 bvec = *(const float4*)(w + (o0 + row) * VAL_ATTNc + k0 + 4 * c4);
            Bs[4 * c4 + 0][row] = bvec.x; Bs[4 * c4 + 1][row] = bvec.y;
            Bs[4 * c4 + 2][row] = bvec.z; Bs[4 * c4 + 3][row] = bvec.w;
        }
        __syncthreads();
#pragma unroll
        for (int kk = 0; kk < 16; kk++) {
            unsigned long long a2[8], b2[4];
#pragma unroll
            for (int i = 0; i < 8; i++) { float av = As[kk][8 * ty + i]; a2[i] = pack2(av, av); }
#pragma unroll
            for (int j = 0; j < 4; j++) {
                float2 bv = *(const float2*)&Bs[kk][2 * tx + 32 * j];
                b2[j] = pack2(bv.x, bv.y);
            }
#pragma unroll
            for (int i = 0; i < 8; i++)
#pragma unroll
                for (int j = 0; j < 4; j++) fma2(acc[i][j], a2[i], b2[j]);
        }
        __syncthreads();
    }
#pragma unroll
    for (int i = 0; i < 8; i++) {
        int m = m0 + 8 * ty + i;
#pragma unroll
        for (int j = 0; j < 4; j++) {
            int o = o0 + 2 * tx + 32 * j;
            float2 v2 = unpack2(acc[i][j]);
            float y0 = v2.x * g_ps[o]     + g_pbb[o];
            float y1 = v2.y * g_ps[o + 1] + g_pbb[o + 1];
            *(float2*)&out[m * DIMc + o] = make_float2(y0, y1);
        }
    }
}

// ---------------- launch ----------------
extern "C" void kernel_launch(void* const* d_in, const int* in_sizes, int n_in,
                              void* d_out, int out_size) {
    (void)in_sizes; (void)n_in; (void)out_size;
    const float* x      = (const float*)d_in[0];
    const float* qkv_w  = (const float*)d_in[1];
    const float* qkv_g  = (const float*)d_in[2];
    const float* qkv_b  = (const float*)d_in[3];
    const float* qkv_m  = (const float*)d_in[4];
    const float* qkv_v  = (const float*)d_in[5];
    const float* ab     = (const float*)d_in[6];
    const float* proj_w = (const float*)d_in[7];
    const float* proj_g = (const float*)d_in[8];
    const float* proj_b = (const float*)d_in[9];
    const float* proj_m = (const float*)d_in[10];
    const float* proj_v = (const float*)d_in[11];
    const int*   idxs   = (const int*)d_in[12];
    float* out = (float*)d_out;

    bn_coef_kernel<<<6, 256>>>(qkv_g, qkv_b, qkv_m, qkv_v, proj_g, proj_b, proj_m, proj_v);
    bias_kernel<<<(Nn * Nn + 255) / 256, 256>>>(ab, idxs);
    qkv_gemm_kernel<<<dim3(196, 12), 256>>>(x, qkv_w);

    const int ATTN_SMEM = (32 * 68 * 2 + 64 * 128 + 64 * 69) * 4;  // 67840 B
    cudaFuncSetAttribute(attn_kernel, cudaFuncAttributeMaxDynamicSharedMemorySize, ATTN_SMEM);
    attn_kernel<<<dim3(13, 8, 32), 256, ATTN_SMEM>>>();

    proj_gemm_kernel<<<dim3(196, 4), 256>>>(proj_w, out);
}